// round 1
// baseline (speedup 1.0000x reference)
#include <cuda_runtime.h>
#include <math.h>

// Shapes (fixed by the problem)
#define B_  2
#define H_  8
#define N_  64
#define TD_ 1024          // T*D = 32*32
#define SCALE_ 32.0f      // sqrt(T*D)

// One block per (b,h,i). 256 threads = 8 warps.
__global__ __launch_bounds__(256, 4)
void mha_fused_kernel(const float* __restrict__ Q,
                      const float* __restrict__ K,
                      const float* __restrict__ V,
                      const int*   __restrict__ mask,
                      float*       __restrict__ out)
{
    const int bx   = blockIdx.x;          // 0 .. B*H*N-1
    const int i    = bx % N_;
    const int bh   = bx / N_;             // 0 .. B*H-1
    const int tid  = threadIdx.x;
    const int lane = tid & 31;
    const int warp = tid >> 5;

    __shared__ float s_attn[N_];          // qk scores -> attn weights

    // ---------------- Phase 1: qk[j] = Q[i]·K[j] / SCALE ----------------
    // Each lane holds 8 float4 of the Q row (stride-32 float4 pattern).
    const float4* Qrow = reinterpret_cast<const float4*>(Q + (size_t)(bh * N_ + i) * TD_);
    float4 q[8];
#pragma unroll
    for (int m = 0; m < 8; ++m) q[m] = Qrow[lane + 32 * m];

    // Warp w handles j = w, w+8, ..., w+56
    for (int j = warp; j < N_; j += 8) {
        const float4* Krow = reinterpret_cast<const float4*>(K + (size_t)(bh * N_ + j) * TD_);
        float dot = 0.0f;
#pragma unroll
        for (int m = 0; m < 8; ++m) {
            float4 k4 = Krow[lane + 32 * m];
            dot += q[m].x * k4.x + q[m].y * k4.y + q[m].z * k4.z + q[m].w * k4.w;
        }
        // warp reduce
#pragma unroll
        for (int o = 16; o > 0; o >>= 1) dot += __shfl_xor_sync(0xffffffffu, dot, o);
        if (lane == 0) {
            int mk = mask[(size_t)(bh * N_ + i) * N_ + j];
            s_attn[j] = (mk == 0) ? -INFINITY : dot * (1.0f / SCALE_);
        }
    }
    __syncthreads();

    // ---------------- Softmax over j (warp 0) ----------------
    if (warp == 0) {
        float v0 = s_attn[lane];
        float v1 = s_attn[lane + 32];
        float m = fmaxf(v0, v1);
#pragma unroll
        for (int o = 16; o > 0; o >>= 1) m = fmaxf(m, __shfl_xor_sync(0xffffffffu, m, o));
        float e0 = expf(v0 - m);
        float e1 = expf(v1 - m);
        float s = e0 + e1;
#pragma unroll
        for (int o = 16; o > 0; o >>= 1) s += __shfl_xor_sync(0xffffffffu, s, o);
        float inv = 1.0f / s;
        s_attn[lane]      = e0 * inv;
        s_attn[lane + 32] = e1 * inv;
    }
    __syncthreads();

    // ---------------- Phase 2: out[tf] = sum_j attn[j] * V[b,h,j,i,tf] ----------------
    // thread tid owns float4 index tid (256 float4 = 1024 floats, exact).
    // V row for (j): V + ((bh*N + j)*N + i)*TD
    const float4* Vbase = reinterpret_cast<const float4*>(V) +
                          ((size_t)bh * N_ * N_ + i) * (TD_ / 4) + tid;
    const size_t jstride = (size_t)N_ * (TD_ / 4);   // in float4 units

    float4 acc = make_float4(0.f, 0.f, 0.f, 0.f);
#pragma unroll 4
    for (int j = 0; j < N_; ++j) {
        float a = s_attn[j];
        float4 v4 = Vbase[(size_t)j * jstride];
        acc.x += a * v4.x;
        acc.y += a * v4.y;
        acc.z += a * v4.z;
        acc.w += a * v4.w;
    }

    float4* Orow = reinterpret_cast<float4*>(out + (size_t)(bh * N_ + i) * TD_);
    Orow[tid] = acc;
}

extern "C" void kernel_launch(void* const* d_in, const int* in_sizes, int n_in,
                              void* d_out, int out_size)
{
    const float* Q    = (const float*)d_in[0];
    const float* K    = (const float*)d_in[1];
    const float* V    = (const float*)d_in[2];
    const int*   mask = (const int*)d_in[3];
    float*       out  = (float*)d_out;

    dim3 grid(B_ * H_ * N_);   // 1024 blocks
    dim3 block(256);
    mha_fused_kernel<<<grid, block>>>(Q, K, V, mask, out);
}